// round 12
// baseline (speedup 1.0000x reference)
#include <cuda_runtime.h>
#include <cuda_bf16.h>
#include <math.h>

// Problem constants: B=2, L=4096, H=8, D=64, FACTOR=5 -> U_part = u = 45
#define L_SEQ 4096
#define NH 8
#define DDIM 64
#define NU 45
#define NS 45
#define NBH 16
#define NIDX (L_SEQ * NS)      // 184320
#define CHUNK 128
#define NCHUNK 32              // 4096 / 128
#define PART_STRIDE 68         // [0]=m, [1]=l, [4..67]=acc (16B-aligned records)
#define NEG_BIG (-1e30f)
#define SKT_STRIDE 132         // K^T/P row stride (mult of 4 -> float4 rows)

// k_attn smem (dynamic): sQt 64x48 | sKT 64x132 (K^T then P 48x132) | sV 128x64
#define SQT_FLOATS (64 * 48)
#define SKT_FLOATS (64 * SKT_STRIDE)
#define SV_FLOATS  (128 * 64)
#define SMEM_BYTES ((SQT_FLOATS + SKT_FLOATS + SV_FLOATS) * 4)   // 78,848 B

// ---------------- scratch (no allocations allowed) ----------------
__device__ int   g_idx[NIDX];
__device__ float g_M[NBH * L_SEQ];
__device__ int   g_topk[NBH * NU];
__device__ float g_part[NBH * NCHUNK * NU * PART_STRIDE]; // 6.3 MB

// ---------------- threefry2x32 (JAX partitionable) ----------------
#define TF_ROUND(x0, x1, r) do { (x0) += (x1); (x1) = ((x1) << (r)) | ((x1) >> (32 - (r))); (x1) ^= (x0); } while (0)

__host__ __device__ inline void tf2x32(unsigned k0, unsigned k1, unsigned &x0, unsigned &x1) {
    unsigned ks0 = k0, ks1 = k1, ks2 = k0 ^ k1 ^ 0x1BD11BDAu;
    x0 += ks0; x1 += ks1;
    TF_ROUND(x0, x1, 13); TF_ROUND(x0, x1, 15); TF_ROUND(x0, x1, 26); TF_ROUND(x0, x1, 6);
    x0 += ks1; x1 += ks2 + 1u;
    TF_ROUND(x0, x1, 17); TF_ROUND(x0, x1, 29); TF_ROUND(x0, x1, 16); TF_ROUND(x0, x1, 24);
    x0 += ks2; x1 += ks0 + 2u;
    TF_ROUND(x0, x1, 13); TF_ROUND(x0, x1, 15); TF_ROUND(x0, x1, 26); TF_ROUND(x0, x1, 6);
    x0 += ks0; x1 += ks1 + 3u;
    TF_ROUND(x0, x1, 17); TF_ROUND(x0, x1, 29); TF_ROUND(x0, x1, 16); TF_ROUND(x0, x1, 24);
    x0 += ks1; x1 += ks2 + 4u;
    TF_ROUND(x0, x1, 13); TF_ROUND(x0, x1, 15); TF_ROUND(x0, x1, 26); TF_ROUND(x0, x1, 6);
    x0 += ks2; x1 += ks0 + 5u;
}

// random_bits: element i uses counter (0, i); output = out0 ^ out1; & 0xFFF.
__global__ void k_idx(unsigned k2a, unsigned k2b) {
    int i = blockIdx.x * blockDim.x + threadIdx.x;
    if (i >= NIDX) return;
    unsigned x0 = 0u, x1 = (unsigned)i;
    tf2x32(k2a, k2b, x0, x1);
    g_idx[i] = (int)((x0 ^ x1) & 0xFFFu);
}

// ---------------- M metric: warp per (b,h,q), half-warp per sample ----------------
__global__ void k_M(const float* __restrict__ Q, const float* __restrict__ K) {
    int warp = (blockIdx.x * blockDim.x + threadIdx.x) >> 5;
    int lane = threadIdx.x & 31;
    if (warp >= NBH * L_SEQ) return;
    int q = warp & (L_SEQ - 1);
    int bh = warp >> 12;
    int b = bh >> 3, h = bh & 7;
    int hw = lane >> 4, ld = lane & 15;

    float4 qv = *(const float4*)(Q + ((size_t)(b * L_SEQ + q) * NH + h) * DDIM + 4 * ld);
    const float* Kb = K + (size_t)b * (L_SEQ * NH * DDIM) + (size_t)h * DDIM;
    const int* idxp = g_idx + q * NS;

    float mx = NEG_BIG, sm = 0.0f;
#pragma unroll
    for (int s = 0; s < NS; s += 2) {
        int s0 = s + hw;
        int i = (s0 < NS) ? s0 : (NS - 1);
        int k = idxp[i];
        float4 kv = *(const float4*)(Kb + (size_t)k * (NH * DDIM) + 4 * ld);
        float p = qv.x * kv.x + qv.y * kv.y + qv.z * kv.z + qv.w * kv.w;
        p += __shfl_xor_sync(0xFFFFFFFFu, p, 8);
        p += __shfl_xor_sync(0xFFFFFFFFu, p, 4);
        p += __shfl_xor_sync(0xFFFFFFFFu, p, 2);
        p += __shfl_xor_sync(0xFFFFFFFFu, p, 1);
        if (s0 < NS) { mx = fmaxf(mx, p); sm += p; }
    }
    mx = fmaxf(mx, __shfl_xor_sync(0xFFFFFFFFu, mx, 16));
    sm += __shfl_xor_sync(0xFFFFFFFFu, sm, 16);
    if (lane == 0) g_M[warp] = mx - sm * (1.0f / (float)L_SEQ);
}

// ---------------- exact top-45: hierarchical max-tree, warp-0 selection loop ----------------
__global__ void __launch_bounds__(1024) k_topk() {
    __shared__ unsigned long long sk[L_SEQ];
    __shared__ unsigned long long gmax[128];
    int bh = blockIdx.x;
    int t = threadIdx.x, lane = t & 31, w = t >> 5;

    for (int i = t; i < L_SEQ; i += 1024) {
        unsigned u = __float_as_uint(g_M[bh * L_SEQ + i]);
        u = (u & 0x80000000u) ? ~u : (u | 0x80000000u);
        sk[i] = ((unsigned long long)u << 32) | (unsigned)(L_SEQ - 1 - i);
    }
    __syncthreads();

#pragma unroll
    for (int g = w; g < 128; g += 32) {
        unsigned long long v = sk[g * 32 + lane];
#pragma unroll
        for (int off = 16; off; off >>= 1) {
            unsigned long long o = __shfl_xor_sync(0xFFFFFFFFu, v, off);
            v = (o > v) ? o : v;
        }
        if (lane == 0) gmax[g] = v;
    }
    __syncthreads();

    if (w == 0) {
        for (int it = 0; it < NU; it++) {
            unsigned long long a = gmax[lane], b2 = gmax[lane + 32];
            unsigned long long c = gmax[lane + 64], d = gmax[lane + 96];
            unsigned long long v = a > b2 ? a : b2;
            unsigned long long v2 = c > d ? c : d;
            v = v > v2 ? v : v2;
#pragma unroll
            for (int off = 16; off; off >>= 1) {
                unsigned long long o = __shfl_xor_sync(0xFFFFFFFFu, v, off);
                v = (o > v) ? o : v;
            }
            int q = (L_SEQ - 1) - (int)(v & 0xFFFFFFFFu);
            if (lane == 0) {
                g_topk[bh * NU + it] = q;
                sk[q] = 0ull;
            }
            __syncwarp();
            int g = q >> 5;
            unsigned long long x = sk[g * 32 + lane];
#pragma unroll
            for (int off = 16; off; off >>= 1) {
                unsigned long long o = __shfl_xor_sync(0xFFFFFFFFu, x, off);
                x = (o > x) ? o : x;
            }
            if (lane == 0) gmax[g] = x;
            __syncwarp();
        }
    }
}

// ---------------- attention partials: 128 threads, 12u x 4k / 6u x 4d tiles ----------------
// Phase A: warp w -> u [12w, 12w+12), lane -> 4 k; 48 FMA per 40 B smem.
// Phase B: thread (gu=t>>4, gd=t&15) -> 6u x 4d; 24 FMA per 40 B smem.
__global__ void __launch_bounds__(128) k_attn(const float* __restrict__ Q, const float* __restrict__ K,
                       const float* __restrict__ V, const int* __restrict__ mask) {
    extern __shared__ float smem[];
    float* sQt = smem;                       // [d][u] stride 48
    float* sKT = smem + SQT_FLOATS;          // [d][k] stride 132; reused as P [u][k]
    float* sV  = smem + SQT_FLOATS + SKT_FLOATS; // [k][d] stride 64

    int bh = blockIdx.x >> 5, c = blockIdx.x & 31;
    int b = bh >> 3, h = bh & 7;
    int t = threadIdx.x;
    int lane = t & 31, w = t >> 5;
    int k0 = c * CHUNK;

    // ---- load tiles (128 threads) ----
    for (int i = t; i < 64 * 48; i += 128) {
        int d = i / 48, u = i - d * 48;
        float v = 0.0f;
        if (u < NU) {
            int q = g_topk[bh * NU + u];
            v = Q[((size_t)(b * L_SEQ + q) * NH + h) * DDIM + d];
        }
        sQt[i] = v;
    }
    for (int i = t; i < CHUNK * 64; i += 128) {
        int d = i & 63, k = i >> 6;          // coalesced LDG over d
        sKT[d * SKT_STRIDE + k] = K[((size_t)(b * L_SEQ + k0 + k) * NH + h) * DDIM + d];
    }
    for (int i = t; i < CHUNK * 64; i += 128) {
        int d = i & 63, k = i >> 6;
        sV[(k << 6) + d] = V[((size_t)(b * L_SEQ + k0 + k) * NH + h) * DDIM + d];
    }
    __syncthreads();

    // ---- phase A: S = Q_sel @ K^T, 12u x 4k per thread ----
    float acc[12][4];
#pragma unroll
    for (int i = 0; i < 12; i++)
#pragma unroll
        for (int j = 0; j < 4; j++) acc[i][j] = 0.0f;

#pragma unroll 2
    for (int d = 0; d < 64; d++) {
        const float* qrow = &sQt[d * 48 + 12 * w];
        float4 kv = *(float4*)&sKT[d * SKT_STRIDE + 4 * lane];
        float2 qp[6];
#pragma unroll
        for (int p = 0; p < 6; p++) qp[p] = *(float2*)&qrow[2 * p];
#pragma unroll
        for (int p = 0; p < 6; p++) {
            float qa = qp[p].x, qb = qp[p].y;
            acc[2*p][0]   += qa * kv.x; acc[2*p][1]   += qa * kv.y; acc[2*p][2]   += qa * kv.z; acc[2*p][3]   += qa * kv.w;
            acc[2*p+1][0] += qb * kv.x; acc[2*p+1][1] += qb * kv.y; acc[2*p+1][2] += qb * kv.z; acc[2*p+1][3] += qb * kv.w;
        }
    }

    // mask + scale
    int4 mk = *(const int4*)&mask[b * L_SEQ + k0 + 4 * lane];
#pragma unroll
    for (int i = 0; i < 12; i++) {
        acc[i][0] = mk.x ? acc[i][0] * 0.125f : NEG_BIG;
        acc[i][1] = mk.y ? acc[i][1] * 0.125f : NEG_BIG;
        acc[i][2] = mk.z ? acc[i][2] * 0.125f : NEG_BIG;
        acc[i][3] = mk.w ? acc[i][3] * 0.125f : NEG_BIG;
    }

    // softmax stats: full-warp (warp spans all 128 k for its 12 u)
#pragma unroll
    for (int i = 0; i < 12; i++) {
        float m = fmaxf(fmaxf(acc[i][0], acc[i][1]), fmaxf(acc[i][2], acc[i][3]));
#pragma unroll
        for (int off = 16; off; off >>= 1)
            m = fmaxf(m, __shfl_xor_sync(0xFFFFFFFFu, m, off));
        float l = 0.0f;
#pragma unroll
        for (int j = 0; j < 4; j++) {
            float e = (acc[i][j] <= 0.5f * NEG_BIG) ? 0.0f : __expf(acc[i][j] - m);
            acc[i][j] = e;
            l += e;
        }
#pragma unroll
        for (int off = 16; off; off >>= 1)
            l += __shfl_xor_sync(0xFFFFFFFFu, l, off);
        int u = 12 * w + i;
        if (lane == 0 && u < NU) {
            float* part = g_part + ((size_t)blockIdx.x * NU + u) * PART_STRIDE;
            part[0] = m;
            part[1] = l;
        }
    }
    __syncthreads();   // all reads of sKT (K^T) done

    // write P into sKT ([u][k])
#pragma unroll
    for (int i = 0; i < 12; i++) {
        int u = 12 * w + i;
        *(float4*)&sKT[u * SKT_STRIDE + 4 * lane] = make_float4(acc[i][0], acc[i][1], acc[i][2], acc[i][3]);
    }
    __syncthreads();

    // ---- phase B: O_partial = P @ V, 6u x 4d per thread ----
    int gu = t >> 4, gd = t & 15;
    float ob[6][4];
#pragma unroll
    for (int i = 0; i < 6; i++)
#pragma unroll
        for (int j = 0; j < 4; j++) ob[i][j] = 0.0f;

#pragma unroll 4
    for (int kk = 0; kk < CHUNK; kk++) {
        float4 vv = *(float4*)&sV[(kk << 6) + 4 * gd];
        float p0 = sKT[(6 * gu + 0) * SKT_STRIDE + kk];
        float p1 = sKT[(6 * gu + 1) * SKT_STRIDE + kk];
        float p2 = sKT[(6 * gu + 2) * SKT_STRIDE + kk];
        float p3 = sKT[(6 * gu + 3) * SKT_STRIDE + kk];
        float p4 = sKT[(6 * gu + 4) * SKT_STRIDE + kk];
        float p5 = sKT[(6 * gu + 5) * SKT_STRIDE + kk];
        ob[0][0] += p0 * vv.x; ob[0][1] += p0 * vv.y; ob[0][2] += p0 * vv.z; ob[0][3] += p0 * vv.w;
        ob[1][0] += p1 * vv.x; ob[1][1] += p1 * vv.y; ob[1][2] += p1 * vv.z; ob[1][3] += p1 * vv.w;
        ob[2][0] += p2 * vv.x; ob[2][1] += p2 * vv.y; ob[2][2] += p2 * vv.z; ob[2][3] += p2 * vv.w;
        ob[3][0] += p3 * vv.x; ob[3][1] += p3 * vv.y; ob[3][2] += p3 * vv.z; ob[3][3] += p3 * vv.w;
        ob[4][0] += p4 * vv.x; ob[4][1] += p4 * vv.y; ob[4][2] += p4 * vv.z; ob[4][3] += p4 * vv.w;
        ob[5][0] += p5 * vv.x; ob[5][1] += p5 * vv.y; ob[5][2] += p5 * vv.z; ob[5][3] += p5 * vv.w;
    }
#pragma unroll
    for (int i = 0; i < 6; i++) {
        int u = 6 * gu + i;
        if (u < NU) {
            float* part = g_part + ((size_t)blockIdx.x * NU + u) * PART_STRIDE;
            *(float4*)&part[4 + 4 * gd] = make_float4(ob[i][0], ob[i][1], ob[i][2], ob[i][3]);
        }
    }
}

// ---------------- combine split-K partials ----------------
__global__ void k_comb(float* __restrict__ out) {
    int bu = blockIdx.x;
    int bh = bu / NU, u = bu % NU;
    int b = bh >> 3, h = bh & 7;
    int d = threadIdx.x;

    float m = NEG_BIG;
#pragma unroll 8
    for (int c = 0; c < NCHUNK; c++)
        m = fmaxf(m, g_part[((size_t)(bh * NCHUNK + c) * NU + u) * PART_STRIDE]);
    float l = 0.0f, acc = 0.0f;
#pragma unroll 8
    for (int c = 0; c < NCHUNK; c++) {
        const float* part = g_part + ((size_t)(bh * NCHUNK + c) * NU + u) * PART_STRIDE;
        float mc = part[0];
        float sc = (mc <= 0.5f * NEG_BIG) ? 0.0f : __expf(mc - m);
        l += part[1] * sc;
        acc += sc * part[4 + d];
    }
    out[((size_t)(b * NU + u) * NH + h) * DDIM + d] = acc / l;
}

// ---------------- launch ----------------
extern "C" void kernel_launch(void* const* d_in, const int* in_sizes, int n_in,
                              void* d_out, int out_size) {
    const float* Q = (const float*)d_in[0];
    const float* K = (const float*)d_in[1];
    const float* V = (const float*)d_in[2];
    const int* mask = (const int*)d_in[3];
    float* out = (float*)d_out;

    cudaFuncSetAttribute(k_attn, cudaFuncAttributeMaxDynamicSharedMemorySize, SMEM_BYTES);

    // lower_key = 2nd child of foldlike split(key(1)) = tf2x32(key=(0,1), ctr=(0,1))
    unsigned s0 = 0u, s1 = 1u;
    tf2x32(0u, 1u, s0, s1);

    k_idx<<<(NIDX + 255) / 256, 256>>>(s0, s1);
    k_M<<<(NBH * L_SEQ) / 8, 256>>>(Q, K);
    k_topk<<<NBH, 1024>>>();
    k_attn<<<NBH * NCHUNK, 128, SMEM_BYTES>>>(Q, K, V, mask);
    k_comb<<<NBH * NU, 64>>>(out);
}

// round 15
// speedup vs baseline: 1.0186x; 1.0186x over previous
#include <cuda_runtime.h>
#include <cuda_bf16.h>
#include <math.h>

// Problem constants: B=2, L=4096, H=8, D=64, FACTOR=5 -> U_part = u = 45
#define L_SEQ 4096
#define NH 8
#define DDIM 64
#define NU 45
#define NS 45
#define NBH 16
#define NIDX (L_SEQ * NS)      // 184320
#define CHUNK 128              // keys per inner pass
#define NBLK 16                // blocks per bh (each covers 256 keys)
#define PART_STRIDE 68         // [0]=m, [1]=l, [4..67]=acc (16B-aligned records)
#define NEG_BIG (-1e30f)
#define SKT_STRIDE 132         // K^T/P row stride (mult of 4 -> float4 rows)

// k_attn smem (dynamic): sQt 64x48 | sKT 64x132 | sV 128x64
#define SQT_FLOATS (64 * 48)
#define SKT_FLOATS (64 * SKT_STRIDE)
#define SV_FLOATS  (128 * 64)
#define SMEM_BYTES ((SQT_FLOATS + SKT_FLOATS + SV_FLOATS) * 4)   // 78,848 B

// ---------------- scratch (no allocations allowed) ----------------
__device__ int   g_idx[NIDX];
__device__ float g_M[NBH * L_SEQ];
__device__ int   g_topk[NBH * NU];
__device__ float g_part[NBH * NBLK * NU * PART_STRIDE];

// ---------------- threefry2x32 (JAX partitionable) ----------------
#define TF_ROUND(x0, x1, r) do { (x0) += (x1); (x1) = ((x1) << (r)) | ((x1) >> (32 - (r))); (x1) ^= (x0); } while (0)

__host__ __device__ inline void tf2x32(unsigned k0, unsigned k1, unsigned &x0, unsigned &x1) {
    unsigned ks0 = k0, ks1 = k1, ks2 = k0 ^ k1 ^ 0x1BD11BDAu;
    x0 += ks0; x1 += ks1;
    TF_ROUND(x0, x1, 13); TF_ROUND(x0, x1, 15); TF_ROUND(x0, x1, 26); TF_ROUND(x0, x1, 6);
    x0 += ks1; x1 += ks2 + 1u;
    TF_ROUND(x0, x1, 17); TF_ROUND(x0, x1, 29); TF_ROUND(x0, x1, 16); TF_ROUND(x0, x1, 24);
    x0 += ks2; x1 += ks0 + 2u;
    TF_ROUND(x0, x1, 13); TF_ROUND(x0, x1, 15); TF_ROUND(x0, x1, 26); TF_ROUND(x0, x1, 6);
    x0 += ks0; x1 += ks1 + 3u;
    TF_ROUND(x0, x1, 17); TF_ROUND(x0, x1, 29); TF_ROUND(x0, x1, 16); TF_ROUND(x0, x1, 24);
    x0 += ks1; x1 += ks2 + 4u;
    TF_ROUND(x0, x1, 13); TF_ROUND(x0, x1, 15); TF_ROUND(x0, x1, 26); TF_ROUND(x0, x1, 6);
    x0 += ks2; x1 += ks0 + 5u;
}

// random_bits: element i uses counter (0, i); output = out0 ^ out1; & 0xFFF.
__global__ void k_idx(unsigned k2a, unsigned k2b) {
    int i = blockIdx.x * blockDim.x + threadIdx.x;
    if (i >= NIDX) return;
    unsigned x0 = 0u, x1 = (unsigned)i;
    tf2x32(k2a, k2b, x0, x1);
    g_idx[i] = (int)((x0 ^ x1) & 0xFFFu);
}

// ---------------- M metric: warp per (b,h,q), half-warp per sample ----------------
__global__ void k_M(const float* __restrict__ Q, const float* __restrict__ K) {
    int warp = (blockIdx.x * blockDim.x + threadIdx.x) >> 5;
    int lane = threadIdx.x & 31;
    if (warp >= NBH * L_SEQ) return;
    int q = warp & (L_SEQ - 1);
    int bh = warp >> 12;
    int b = bh >> 3, h = bh & 7;
    int hw = lane >> 4, ld = lane & 15;

    float4 qv = *(const float4*)(Q + ((size_t)(b * L_SEQ + q) * NH + h) * DDIM + 4 * ld);
    const float* Kb = K + (size_t)b * (L_SEQ * NH * DDIM) + (size_t)h * DDIM;
    const int* idxp = g_idx + q * NS;

    float mx = NEG_BIG, sm = 0.0f;
#pragma unroll
    for (int s = 0; s < NS; s += 2) {
        int s0 = s + hw;
        int i = (s0 < NS) ? s0 : (NS - 1);
        int k = idxp[i];
        float4 kv = *(const float4*)(Kb + (size_t)k * (NH * DDIM) + 4 * ld);
        float p = qv.x * kv.x + qv.y * kv.y + qv.z * kv.z + qv.w * kv.w;
        p += __shfl_xor_sync(0xFFFFFFFFu, p, 8);
        p += __shfl_xor_sync(0xFFFFFFFFu, p, 4);
        p += __shfl_xor_sync(0xFFFFFFFFu, p, 2);
        p += __shfl_xor_sync(0xFFFFFFFFu, p, 1);
        if (s0 < NS) { mx = fmaxf(mx, p); sm += p; }
    }
    mx = fmaxf(mx, __shfl_xor_sync(0xFFFFFFFFu, mx, 16));
    sm += __shfl_xor_sync(0xFFFFFFFFu, sm, 16);
    if (lane == 0) g_M[warp] = mx - sm * (1.0f / (float)L_SEQ);
}

// ---------------- exact top-45: hierarchical max-tree, warp-0 selection loop ----------------
__global__ void __launch_bounds__(1024) k_topk() {
    __shared__ unsigned long long sk[L_SEQ];
    __shared__ unsigned long long gmax[128];
    int bh = blockIdx.x;
    int t = threadIdx.x, lane = t & 31, w = t >> 5;

    for (int i = t; i < L_SEQ; i += 1024) {
        unsigned u = __float_as_uint(g_M[bh * L_SEQ + i]);
        u = (u & 0x80000000u) ? ~u : (u | 0x80000000u);
        sk[i] = ((unsigned long long)u << 32) | (unsigned)(L_SEQ - 1 - i);
    }
    __syncthreads();

#pragma unroll
    for (int g = w; g < 128; g += 32) {
        unsigned long long v = sk[g * 32 + lane];
#pragma unroll
        for (int off = 16; off; off >>= 1) {
            unsigned long long o = __shfl_xor_sync(0xFFFFFFFFu, v, off);
            v = (o > v) ? o : v;
        }
        if (lane == 0) gmax[g] = v;
    }
    __syncthreads();

    if (w == 0) {
        for (int it = 0; it < NU; it++) {
            unsigned long long a = gmax[lane], b2 = gmax[lane + 32];
            unsigned long long c = gmax[lane + 64], d = gmax[lane + 96];
            unsigned long long v = a > b2 ? a : b2;
            unsigned long long v2 = c > d ? c : d;
            v = v > v2 ? v : v2;
#pragma unroll
            for (int off = 16; off; off >>= 1) {
                unsigned long long o = __shfl_xor_sync(0xFFFFFFFFu, v, off);
                v = (o > v) ? o : v;
            }
            int q = (L_SEQ - 1) - (int)(v & 0xFFFFFFFFu);
            if (lane == 0) {
                g_topk[bh * NU + it] = q;
                sk[q] = 0ull;
            }
            __syncwarp();
            int g = q >> 5;
            unsigned long long x = sk[g * 32 + lane];
#pragma unroll
            for (int off = 16; off; off >>= 1) {
                unsigned long long o = __shfl_xor_sync(0xFFFFFFFFu, x, off);
                x = (o > x) ? o : x;
            }
            if (lane == 0) gmax[g] = x;
            __syncwarp();
        }
    }
}

// ---------------- attention partials: 256 thr, 2 chunks/block, online softmax ----------------
// Block = (bh, 256-key group). R11 tiling per chunk: tk = t&31 (4k), tu = t>>5 (6u).
__global__ void __launch_bounds__(256) k_attn(const float* __restrict__ Q, const float* __restrict__ K,
                       const float* __restrict__ V, const int* __restrict__ mask) {
    extern __shared__ float smem[];
    float* sQt = smem;                       // [d][u] stride 48
    float* sKT = smem + SQT_FLOATS;          // [d][k] stride 132; reused as P [u][k]
    float* sV  = smem + SQT_FLOATS + SKT_FLOATS; // [k][d] stride 64

    int bh = blockIdx.x >> 4, cg = blockIdx.x & 15;
    int b = bh >> 3, h = bh & 7;
    int t = threadIdx.x;
    int tk = t & 31, tu = t >> 5;

    // ---- load Q tile once ----
    for (int i = t; i < 64 * 48; i += 256) {
        int d = i / 48, u = i - d * 48;
        float v = 0.0f;
        if (u < NU) {
            int q = g_topk[bh * NU + u];
            v = Q[((size_t)(b * L_SEQ + q) * NH + h) * DDIM + d];
        }
        sQt[i] = v;
    }

    float m_i[6], l_i[6];
    float2 ob[6];
#pragma unroll
    for (int i = 0; i < 6; i++) { m_i[i] = NEG_BIG; l_i[i] = 0.0f; ob[i] = make_float2(0.0f, 0.0f); }

    for (int half = 0; half < 2; half++) {
        int k0 = cg * 256 + half * CHUNK;
        if (half) __syncthreads();           // prior phase-B reads done before overwrite
        for (int i = t; i < CHUNK * 64; i += 256) {
            int k = i >> 6, d = i & 63;
            sKT[d * SKT_STRIDE + k] = K[((size_t)(b * L_SEQ + k0 + k) * NH + h) * DDIM + d];
        }
        for (int i = t; i < CHUNK * 64; i += 256) {
            int k = i >> 6, d = i & 63;
            sV[(k << 6) + d] = V[((size_t)(b * L_SEQ + k0 + k) * NH + h) * DDIM + d];
        }
        __syncthreads();

        // ---- scores: 6u x 4k per thread ----
        float acc[6][4];
#pragma unroll
        for (int i = 0; i < 6; i++)
#pragma unroll
            for (int j = 0; j < 4; j++) acc[i][j] = 0.0f;

#pragma unroll 4
        for (int d = 0; d < 64; d++) {
            float2 q01 = *(float2*)&sQt[d * 48 + 6 * tu];
            float2 q23 = *(float2*)&sQt[d * 48 + 6 * tu + 2];
            float2 q45 = *(float2*)&sQt[d * 48 + 6 * tu + 4];
            float4 kv = *(float4*)&sKT[d * SKT_STRIDE + 4 * tk];
            acc[0][0] += q01.x * kv.x; acc[0][1] += q01.x * kv.y; acc[0][2] += q01.x * kv.z; acc[0][3] += q01.x * kv.w;
            acc[1][0] += q01.y * kv.x; acc[1][1] += q01.y * kv.y; acc[1][2] += q01.y * kv.z; acc[1][3] += q01.y * kv.w;
            acc[2][0] += q23.x * kv.x; acc[2][1] += q23.x * kv.y; acc[2][2] += q23.x * kv.z; acc[2][3] += q23.x * kv.w;
            acc[3][0] += q23.y * kv.x; acc[3][1] += q23.y * kv.y; acc[3][2] += q23.y * kv.z; acc[3][3] += q23.y * kv.w;
            acc[4][0] += q45.x * kv.x; acc[4][1] += q45.x * kv.y; acc[4][2] += q45.x * kv.z; acc[4][3] += q45.x * kv.w;
            acc[5][0] += q45.y * kv.x; acc[5][1] += q45.y * kv.y; acc[5][2] += q45.y * kv.z; acc[5][3] += q45.y * kv.w;
        }

        int4 mk = *(const int4*)&mask[b * L_SEQ + k0 + 4 * tk];
#pragma unroll
        for (int i = 0; i < 6; i++) {
            acc[i][0] = mk.x ? acc[i][0] * 0.125f : NEG_BIG;
            acc[i][1] = mk.y ? acc[i][1] * 0.125f : NEG_BIG;
            acc[i][2] = mk.z ? acc[i][2] * 0.125f : NEG_BIG;
            acc[i][3] = mk.w ? acc[i][3] * 0.125f : NEG_BIG;
        }

        // ---- online softmax merge (warp == tu group) ----
#pragma unroll
        for (int i = 0; i < 6; i++) {
            float m = fmaxf(fmaxf(acc[i][0], acc[i][1]), fmaxf(acc[i][2], acc[i][3]));
#pragma unroll
            for (int off = 16; off; off >>= 1)
                m = fmaxf(m, __shfl_xor_sync(0xFFFFFFFFu, m, off));
            float newm = fmaxf(m_i[i], m);
            float l = 0.0f;
#pragma unroll
            for (int j = 0; j < 4; j++) {
                float e = (acc[i][j] <= 0.5f * NEG_BIG) ? 0.0f : __expf(acc[i][j] - newm);
                acc[i][j] = e;
                l += e;
            }
#pragma unroll
            for (int off = 16; off; off >>= 1)
                l += __shfl_xor_sync(0xFFFFFFFFu, l, off);
            float sc = (m_i[i] <= 0.5f * NEG_BIG) ? 0.0f : __expf(m_i[i] - newm);
            l_i[i] = l_i[i] * sc + l;
            ob[i].x *= sc; ob[i].y *= sc;
            m_i[i] = newm;
        }
        __syncthreads();   // all reads of sKT (K^T) done

        // write P into sKT ([u][k])
#pragma unroll
        for (int i = 0; i < 6; i++) {
            int u = 6 * tu + i;
            *(float4*)&sKT[u * SKT_STRIDE + 4 * tk] = make_float4(acc[i][0], acc[i][1], acc[i][2], acc[i][3]);
        }
        __syncthreads();

        // ---- accumulate O: 6u x 2d per thread ----
#pragma unroll 4
        for (int kk = 0; kk < CHUNK; kk++) {
            float2 vv = *(float2*)&sV[(kk << 6) + 2 * tk];
            float p0 = sKT[(6 * tu + 0) * SKT_STRIDE + kk];
            float p1 = sKT[(6 * tu + 1) * SKT_STRIDE + kk];
            float p2 = sKT[(6 * tu + 2) * SKT_STRIDE + kk];
            float p3 = sKT[(6 * tu + 3) * SKT_STRIDE + kk];
            float p4 = sKT[(6 * tu + 4) * SKT_STRIDE + kk];
            float p5 = sKT[(6 * tu + 5) * SKT_STRIDE + kk];
            ob[0].x += p0 * vv.x; ob[0].y += p0 * vv.y;
            ob[1].x += p1 * vv.x; ob[1].y += p1 * vv.y;
            ob[2].x += p2 * vv.x; ob[2].y += p2 * vv.y;
            ob[3].x += p3 * vv.x; ob[3].y += p3 * vv.y;
            ob[4].x += p4 * vv.x; ob[4].y += p4 * vv.y;
            ob[5].x += p5 * vv.x; ob[5].y += p5 * vv.y;
        }
    }

    // ---- write partials ----
#pragma unroll
    for (int i = 0; i < 6; i++) {
        int u = 6 * tu + i;
        if (u < NU) {
            float* part = g_part + ((size_t)blockIdx.x * NU + u) * PART_STRIDE;
            if (tk == 0) { part[0] = m_i[i]; part[1] = l_i[i]; }
            *(float2*)&part[4 + 2 * tk] = ob[i];
        }
    }
}

// ---------------- combine split-K partials (16 per bh) ----------------
__global__ void k_comb(float* __restrict__ out) {
    int bu = blockIdx.x;
    int bh = bu / NU, u = bu % NU;
    int b = bh >> 3, h = bh & 7;
    int d = threadIdx.x;

    float m = NEG_BIG;
#pragma unroll
    for (int c = 0; c < NBLK; c++)
        m = fmaxf(m, g_part[((size_t)(bh * NBLK + c) * NU + u) * PART_STRIDE]);
    float l = 0.0f, acc = 0.0f;
#pragma unroll
    for (int c = 0; c < NBLK; c++) {
        const float* part = g_part + ((size_t)(bh * NBLK + c) * NU + u) * PART_STRIDE;
        float mc = part[0];
        float sc = (mc <= 0.5f * NEG_BIG) ? 0.0f : __expf(mc - m);
        l += part[1] * sc;
        acc += sc * part[4 + d];
    }
    out[((size_t)(b * NU + u) * NH + h) * DDIM + d] = acc / l;
}

// ---------------- launch ----------------
extern "C" void kernel_launch(void* const* d_in, const int* in_sizes, int n_in,
                              void* d_out, int out_size) {
    const float* Q = (const float*)d_in[0];
    const float* K = (const float*)d_in[1];
    const float* V = (const float*)d_in[2];
    const int* mask = (const int*)d_in[3];
    float* out = (float*)d_out;

    cudaFuncSetAttribute(k_attn, cudaFuncAttributeMaxDynamicSharedMemorySize, SMEM_BYTES);

    // lower_key = 2nd child of foldlike split(key(1)) = tf2x32(key=(0,1), ctr=(0,1))
    unsigned s0 = 0u, s1 = 1u;
    tf2x32(0u, 1u, s0, s1);

    k_idx<<<(NIDX + 255) / 256, 256>>>(s0, s1);
    k_M<<<(NBH * L_SEQ) / 8, 256>>>(Q, K);
    k_topk<<<NBH, 1024>>>();
    k_attn<<<NBH * NBLK, 256, SMEM_BYTES>>>(Q, K, V, mask);
    k_comb<<<NBH * NU, 64>>>(out);
}